// round 15
// baseline (speedup 1.0000x reference)
#include <cuda_runtime.h>
#include <cuda_bf16.h>
#include <cuda_fp8.h>
#include <cstdint>

// Problem constants
#define BATCH   2
#define SEQ     1024
#define DMODEL  1024
#define DINNER  2048
#define DTRANK  64
#define NSTATE  16
#define TOKENS  (BATCH*SEQ)          // 2048
#define NSPLIT  8                    // split-K for xproj

// ---------------- scratch (device globals; no allocation allowed) ----------
__device__ __nv_bfloat16 g_ln_bf [TOKENS * DMODEL];
__device__ __nv_bfloat16 g_xz    [TOKENS * 2 * DINNER];     // bf16 (xs | z)
__device__ float         g_xc    [2 * TOKENS * DINNER];
__device__ __nv_bfloat16 g_xc_bf [2 * TOKENS * DINNER];
__device__ float         g_xpart [2 * NSPLIT * TOKENS * 96];
__device__ float         g_xdbl  [2 * TOKENS * 96];
__device__ __nv_bfloat16 g_xdbl_bf[2 * TOKENS * DTRANK];
__device__ float         g_dt    [2 * TOKENS * DINNER];
__device__ uint8_t       g_ycat8 [TOKENS * 2 * DINNER];     // e4m3
__device__ __nv_bfloat16 g_ym_bf [TOKENS * DINNER];
// pre-transposed weights, [N][K] layout
__device__ __nv_bfloat16 g_w_in   [4096 * 1024];
__device__ uint8_t       g_w_merge8[2048 * 4096];           // e4m3
__device__ __nv_bfloat16 g_w_out  [1024 * 2048];
__device__ __nv_bfloat16 g_w_dt0  [2048 * 64];
__device__ __nv_bfloat16 g_w_dt1  [2048 * 64];
__device__ __nv_bfloat16 g_w_xp0  [96 * 2048];
__device__ __nv_bfloat16 g_w_xp1  [96 * 2048];

// ---------------- streams/events for graph-parallel branches --------------
static cudaStream_t g_s1 = nullptr, g_s2 = nullptr;
static cudaEvent_t  g_ev[8];
static struct GInit {
    GInit() {
        cudaStreamCreateWithFlags(&g_s1, cudaStreamNonBlocking);
        cudaStreamCreateWithFlags(&g_s2, cudaStreamNonBlocking);
        for (int i = 0; i < 8; i++)
            cudaEventCreateWithFlags(&g_ev[i], cudaEventDisableTiming);
    }
} g_ginit;

#define PADROW 40      // bf16 elems per smem row (32 data + 8 pad); 80B
#define PADROW8 80     // bytes per fp8 smem row (64 data + 16 pad)

// ---------------- shared epilogue ---------------------------------------
// Modes: 0 fp32 out, 1 bf16 out, 2 softplus(v+aux[c]) fp32,
// 3 v*silu(bf16 aux[r,c]) -> bf16, 4 v+aux[r,c] fp32.
__device__ __forceinline__ void epi_store(
    int mode, float v, int r, int c, int ldc, int ldaux,
    float* Cf, __nv_bfloat16* Cb, const float* auxf, const __nv_bfloat16* auxb)
{
    if (mode == 0) {
        Cf[(size_t)r * ldc + c] = v;
    } else if (mode == 1) {
        Cb[(size_t)r * ldc + c] = __float2bfloat16(v);
    } else if (mode == 2) {
        v += auxf[c];
        v = (v > 20.f) ? v : log1pf(__expf(v));
        Cf[(size_t)r * ldc + c] = v;
    } else if (mode == 3) {
        float z = __bfloat162float(auxb[(size_t)r * ldaux + c]);
        v *= z / (1.f + __expf(-z));
        Cb[(size_t)r * ldc + c] = __float2bfloat16(v);
    } else {
        v += auxf[(size_t)r * ldaux + c];
        Cf[(size_t)r * ldc + c] = v;
    }
}

// ================================================================ GEMM v1 (bf16)
__global__ void __launch_bounds__(256) gemm_bf16(
    int M, int N, int Ksplit,
    const __nv_bfloat16* __restrict__ A, int lda,
    const __nv_bfloat16* __restrict__ B, int ldb,
    void* __restrict__ Cv, int ldc, size_t splitStride,
    int mode, const void* __restrict__ aux, int ldaux)
{
    __shared__ __nv_bfloat16 As[2][128 * PADROW];
    __shared__ __nv_bfloat16 Bs[2][128 * PADROW];

    const int tid  = threadIdx.x;
    const int lane = tid & 31;
    const int warp = tid >> 5;
    const int wm   = warp >> 2;
    const int wn   = warp & 3;
    const int g    = lane >> 2;
    const int t4   = lane & 3;

    const int bM = blockIdx.y * 128;
    const int bN = blockIdx.x * 128;
    const int kbase0 = blockIdx.z * Ksplit;
    const int niter = Ksplit / 32;

    const int r0s = tid >> 2;
    const int p0s = tid & 3;

    float acc[4][4][4];
#pragma unroll
    for (int i = 0; i < 4; i++)
#pragma unroll
        for (int j = 0; j < 4; j++)
#pragma unroll
            for (int q = 0; q < 4; q++) acc[i][j][q] = 0.f;

    const uint4 z4 = make_uint4(0, 0, 0, 0);

    {
        const int kb = kbase0;
#pragma unroll
        for (int i = 0; i < 2; i++) {
            int row = r0s + i * 64;
            uint4 va = *(const uint4*)(A + (size_t)(bM + row) * lda + kb + p0s * 8);
            *(uint4*)&As[0][row * PADROW + p0s * 8] = va;
            uint4 vb = (bN + row < N)
                ? *(const uint4*)(B + (size_t)(bN + row) * ldb + kb + p0s * 8) : z4;
            *(uint4*)&Bs[0][row * PADROW + p0s * 8] = vb;
        }
    }
    __syncthreads();

    for (int it = 0; it < niter; ++it) {
        const int buf = it & 1;
        const bool more = (it + 1) < niter;
        uint4 ra[2], rb[2];
        if (more) {
            const int kb = kbase0 + (it + 1) * 32;
#pragma unroll
            for (int i = 0; i < 2; i++) {
                int row = r0s + i * 64;
                ra[i] = *(const uint4*)(A + (size_t)(bM + row) * lda + kb + p0s * 8);
                rb[i] = (bN + row < N)
                    ? *(const uint4*)(B + (size_t)(bN + row) * ldb + kb + p0s * 8) : z4;
            }
        }

        const __nv_bfloat16* sa = As[buf];
        const __nv_bfloat16* sb = Bs[buf];
#pragma unroll
        for (int s = 0; s < 2; s++) {
            const int k0 = s * 16;
            uint32_t af[4][4];
#pragma unroll
            for (int im = 0; im < 4; im++) {
                int base = (wm * 64 + im * 16 + g) * PADROW + k0 + t4 * 2;
                af[im][0] = *(const uint32_t*)&sa[base];
                af[im][1] = *(const uint32_t*)&sa[base + 8 * PADROW];
                af[im][2] = *(const uint32_t*)&sa[base + 8];
                af[im][3] = *(const uint32_t*)&sa[base + 8 * PADROW + 8];
            }
            uint32_t bf[4][2];
#pragma unroll
            for (int in_ = 0; in_ < 4; in_++) {
                int base = (wn * 32 + in_ * 8 + g) * PADROW + k0 + t4 * 2;
                bf[in_][0] = *(const uint32_t*)&sb[base];
                bf[in_][1] = *(const uint32_t*)&sb[base + 8];
            }
#pragma unroll
            for (int im = 0; im < 4; im++)
#pragma unroll
                for (int in_ = 0; in_ < 4; in_++) {
                    asm volatile(
                        "mma.sync.aligned.m16n8k16.row.col.f32.bf16.bf16.f32 "
                        "{%0,%1,%2,%3}, {%4,%5,%6,%7}, {%8,%9}, {%0,%1,%2,%3};"
                        : "+f"(acc[im][in_][0]), "+f"(acc[im][in_][1]),
                          "+f"(acc[im][in_][2]), "+f"(acc[im][in_][3])
                        : "r"(af[im][0]), "r"(af[im][1]), "r"(af[im][2]), "r"(af[im][3]),
                          "r"(bf[in_][0]), "r"(bf[in_][1]));
                }
        }

        if (more) {
            const int nb = buf ^ 1;
#pragma unroll
            for (int i = 0; i < 2; i++) {
                int row = r0s + i * 64;
                *(uint4*)&As[nb][row * PADROW + p0s * 8] = ra[i];
                *(uint4*)&Bs[nb][row * PADROW + p0s * 8] = rb[i];
            }
        }
        __syncthreads();
    }

    float* Cf = (float*)Cv + (size_t)blockIdx.z * splitStride;
    __nv_bfloat16* Cb = (__nv_bfloat16*)Cv;
    const float* auxf = (const float*)aux;
    const __nv_bfloat16* auxb = (const __nv_bfloat16*)aux;
#pragma unroll
    for (int im = 0; im < 4; im++) {
        int rr0 = bM + wm * 64 + im * 16 + g;
#pragma unroll
        for (int in_ = 0; in_ < 4; in_++) {
            int cc0 = bN + wn * 32 + in_ * 8 + t4 * 2;
#pragma unroll
            for (int q = 0; q < 4; q++) {
                int r = rr0 + (q >> 1) * 8;
                int c = cc0 + (q & 1);
                if (c >= N) continue;
                epi_store(mode, acc[im][in_][q], r, c, ldc, ldaux, Cf, Cb, auxf, auxb);
            }
        }
    }
}

// ================================================================ GEMM w64 (bf16)
__global__ void __launch_bounds__(128) gemm_w64(
    int M, int N, int Kfull,
    const __nv_bfloat16* __restrict__ A, int lda,
    const __nv_bfloat16* __restrict__ B, int ldb,
    void* __restrict__ Cv, int ldc,
    int mode, const void* __restrict__ aux, int ldaux)
{
    __shared__ __nv_bfloat16 As[2][128 * PADROW];
    __shared__ __nv_bfloat16 Bs[2][128 * PADROW];

    const int tid  = threadIdx.x;
    const int lane = tid & 31;
    const int warp = tid >> 5;
    const int wm   = warp >> 1;
    const int wn   = warp & 1;
    const int g    = lane >> 2;
    const int t4   = lane & 3;

    const int bM = blockIdx.y * 128;
    const int bN = blockIdx.x * 128;
    const int niter = Kfull / 32;

    const int r0s = tid >> 2;
    const int p0s = tid & 3;

    float acc[4][8][4];
#pragma unroll
    for (int i = 0; i < 4; i++)
#pragma unroll
        for (int j = 0; j < 8; j++)
#pragma unroll
            for (int q = 0; q < 4; q++) acc[i][j][q] = 0.f;

    const uint4 z4 = make_uint4(0, 0, 0, 0);

    {
#pragma unroll
        for (int i = 0; i < 4; i++) {
            int row = r0s + i * 32;
            uint4 va = *(const uint4*)(A + (size_t)(bM + row) * lda + p0s * 8);
            *(uint4*)&As[0][row * PADROW + p0s * 8] = va;
            uint4 vb = (bN + row < N)
                ? *(const uint4*)(B + (size_t)(bN + row) * ldb + p0s * 8) : z4;
            *(uint4*)&Bs[0][row * PADROW + p0s * 8] = vb;
        }
    }
    __syncthreads();

    for (int it = 0; it < niter; ++it) {
        const int buf = it & 1;
        const bool more = (it + 1) < niter;
        uint4 ra[4], rb[4];
        if (more) {
            const int kb = (it + 1) * 32;
#pragma unroll
            for (int i = 0; i < 4; i++) {
                int row = r0s + i * 32;
                ra[i] = *(const uint4*)(A + (size_t)(bM + row) * lda + kb + p0s * 8);
                rb[i] = (bN + row < N)
                    ? *(const uint4*)(B + (size_t)(bN + row) * ldb + kb + p0s * 8) : z4;
            }
        }

        const __nv_bfloat16* sa = As[buf];
        const __nv_bfloat16* sb = Bs[buf];
#pragma unroll
        for (int s = 0; s < 2; s++) {
            const int k0 = s * 16;
            uint32_t af[4][4];
#pragma unroll
            for (int im = 0; im < 4; im++) {
                int base = (wm * 64 + im * 16 + g) * PADROW + k0 + t4 * 2;
                af[im][0] = *(const uint32_t*)&sa[base];
                af[im][1] = *(const uint32_t*)&sa[base + 8 * PADROW];
                af[im][2] = *(const uint32_t*)&sa[base + 8];
                af[im][3] = *(const uint32_t*)&sa[base + 8 * PADROW + 8];
            }
            uint32_t bf[8][2];
#pragma unroll
            for (int in_ = 0; in_ < 8; in_++) {
                int base = (wn * 64 + in_ * 8 + g) * PADROW + k0 + t4 * 2;
                bf[in_][0] = *(const uint32_t*)&sb[base];
                bf[in_][1] = *(const uint32_t*)&sb[base + 8];
            }
#pragma unroll
            for (int im = 0; im < 4; im++)
#pragma unroll
                for (int in_ = 0; in_ < 8; in_++) {
                    asm volatile(
                        "mma.sync.aligned.m16n8k16.row.col.f32.bf16.bf16.f32 "
                        "{%0,%1,%2,%3}, {%4,%5,%6,%7}, {%8,%9}, {%0,%1,%2,%3};"
                        : "+f"(acc[im][in_][0]), "+f"(acc[im][in_][1]),
                          "+f"(acc[im][in_][2]), "+f"(acc[im][in_][3])
                        : "r"(af[im][0]), "r"(af[im][1]), "r"(af[im][2]), "r"(af[im][3]),
                          "r"(bf[in_][0]), "r"(bf[in_][1]));
                }
        }

        if (more) {
            const int nb = buf ^ 1;
#pragma unroll
            for (int i = 0; i < 4; i++) {
                int row = r0s + i * 32;
                *(uint4*)&As[nb][row * PADROW + p0s * 8] = ra[i];
                *(uint4*)&Bs[nb][row * PADROW + p0s * 8] = rb[i];
            }
        }
        __syncthreads();
    }

    float* Cf = (float*)Cv;
    __nv_bfloat16* Cb = (__nv_bfloat16*)Cv;
    const float* auxf = (const float*)aux;
    const __nv_bfloat16* auxb = (const __nv_bfloat16*)aux;
#pragma unroll
    for (int im = 0; im < 4; im++) {
        int rr0 = bM + wm * 64 + im * 16 + g;
#pragma unroll
        for (int in_ = 0; in_ < 8; in_++) {
            int cc0 = bN + wn * 64 + in_ * 8 + t4 * 2;
#pragma unroll
            for (int q = 0; q < 4; q++) {
                int r = rr0 + (q >> 1) * 8;
                int c = cc0 + (q & 1);
                if (c >= N) continue;
                epi_store(mode, acc[im][in_][q], r, c, ldc, ldaux, Cf, Cb, auxf, auxb);
            }
        }
    }
}

// ================================================================ GEMM fp8 (e4m3)
// D[M,N] = A[M,K] @ B^T, A:[M][K] e4m3, B:[N][K] e4m3. 256 threads, 8 warps
// (2x4), warp tile 64x32, mma.sync.m16n8k32.e4m3, fp32 accum. BK=64 bytes.
__global__ void __launch_bounds__(256) gemm_fp8(
    int M, int N, int Kfull,
    const uint8_t* __restrict__ A, int lda,
    const uint8_t* __restrict__ B, int ldb,
    void* __restrict__ Cv, int ldc,
    int mode, const void* __restrict__ aux, int ldaux)
{
    __shared__ uint8_t As[2][128 * PADROW8];
    __shared__ uint8_t Bs[2][128 * PADROW8];

    const int tid  = threadIdx.x;
    const int lane = tid & 31;
    const int warp = tid >> 5;
    const int wm   = warp >> 2;
    const int wn   = warp & 3;
    const int g    = lane >> 2;
    const int t4   = lane & 3;

    const int bM = blockIdx.y * 128;
    const int bN = blockIdx.x * 128;
    const int niter = Kfull / 64;

    // staging: tile = 128 rows x 64B = 512 x 16B; 2 per thread
    const int r0s = tid >> 2;             // rows r0s, r0s+64
    const int p0s = tid & 3;              // byte chunk p0s*16

    float acc[4][4][4];
#pragma unroll
    for (int i = 0; i < 4; i++)
#pragma unroll
        for (int j = 0; j < 4; j++)
#pragma unroll
            for (int q = 0; q < 4; q++) acc[i][j][q] = 0.f;

    {
#pragma unroll
        for (int i = 0; i < 2; i++) {
            int row = r0s + i * 64;
            uint4 va = *(const uint4*)(A + (size_t)(bM + row) * lda + p0s * 16);
            *(uint4*)&As[0][row * PADROW8 + p0s * 16] = va;
            uint4 vb = *(const uint4*)(B + (size_t)(bN + row) * ldb + p0s * 16);
            *(uint4*)&Bs[0][row * PADROW8 + p0s * 16] = vb;
        }
    }
    __syncthreads();

    for (int it = 0; it < niter; ++it) {
        const int buf = it & 1;
        const bool more = (it + 1) < niter;
        uint4 ra[2], rb[2];
        if (more) {
            const int kb = (it + 1) * 64;
#pragma unroll
            for (int i = 0; i < 2; i++) {
                int row = r0s + i * 64;
                ra[i] = *(const uint4*)(A + (size_t)(bM + row) * lda + kb + p0s * 16);
                rb[i] = *(const uint4*)(B + (size_t)(bN + row) * ldb + kb + p0s * 16);
            }
        }

        const uint8_t* sa = As[buf];
        const uint8_t* sb = Bs[buf];
#pragma unroll
        for (int s = 0; s < 2; s++) {
            const int k0 = s * 32;
            uint32_t af[4][4];
#pragma unroll
            for (int im = 0; im < 4; im++) {
                int base = (wm * 64 + im * 16 + g) * PADROW8 + k0 + t4 * 4;
                af[im][0] = *(const uint32_t*)&sa[base];
                af[im][1] = *(const uint32_t*)&sa[base + 8 * PADROW8];
                af[im][2] = *(const uint32_t*)&sa[base + 16];
                af[im][3] = *(const uint32_t*)&sa[base + 8 * PADROW8 + 16];
            }
            uint32_t bf[4][2];
#pragma unroll
            for (int in_ = 0; in_ < 4; in_++) {
                int base = (wn * 32 + in_ * 8 + g) * PADROW8 + k0 + t4 * 4;
                bf[in_][0] = *(const uint32_t*)&sb[base];
                bf[in_][1] = *(const uint32_t*)&sb[base + 16];
            }
#pragma unroll
            for (int im = 0; im < 4; im++)
#pragma unroll
                for (int in_ = 0; in_ < 4; in_++) {
                    asm volatile(
                        "mma.sync.aligned.m16n8k32.row.col.f32.e4m3.e4m3.f32 "
                        "{%0,%1,%2,%3}, {%4,%5,%6,%7}, {%8,%9}, {%0,%1,%2,%3};"
                        : "+f"(acc[im][in_][0]), "+f"(acc[im][in_][1]),
                          "+f"(acc[im][in_][2]), "+f"(acc[im][in_][3])
                        : "r"(af[im][0]), "r"(af[im][1]), "r"(af[im][2]), "r"(af[im][3]),
                          "r"(bf[in_][0]), "r"(bf[in_][1]));
                }
        }

        if (more) {
            const int nb = buf ^ 1;
#pragma unroll
            for (int i = 0; i < 2; i++) {
                int row = r0s + i * 64;
                *(uint4*)&As[nb][row * PADROW8 + p0s * 16] = ra[i];
                *(uint4*)&Bs[nb][row * PADROW8 + p0s * 16] = rb[i];
            }
        }
        __syncthreads();
    }

    float* Cf = (float*)Cv;
    __nv_bfloat16* Cb = (__nv_bfloat16*)Cv;
    const float* auxf = (const float*)aux;
    const __nv_bfloat16* auxb = (const __nv_bfloat16*)aux;
#pragma unroll
    for (int im = 0; im < 4; im++) {
        int rr0 = bM + wm * 64 + im * 16 + g;
#pragma unroll
        for (int in_ = 0; in_ < 4; in_++) {
            int cc0 = bN + wn * 32 + in_ * 8 + t4 * 2;
#pragma unroll
            for (int q = 0; q < 4; q++) {
                int r = rr0 + (q >> 1) * 8;
                int c = cc0 + (q & 1);
                if (c >= N) continue;
                epi_store(mode, acc[im][in_][q], r, c, ldc, ldaux, Cf, Cb, auxf, auxb);
            }
        }
    }
}

// ============================================================ weight transposes
__global__ void transpose_bf16(const float* __restrict__ in, __nv_bfloat16* __restrict__ out,
                               int K, int N)
{
    __shared__ float t[32][33];
    int nb = blockIdx.x * 32, kb = blockIdx.y * 32;
    for (int i = threadIdx.y; i < 32; i += 8) {
        int k = kb + i, n = nb + threadIdx.x;
        t[i][threadIdx.x] = (k < K && n < N) ? in[(size_t)k * N + n] : 0.f;
    }
    __syncthreads();
    for (int i = threadIdx.y; i < 32; i += 8) {
        int n = nb + i, k = kb + threadIdx.x;
        if (n < N && k < K) out[(size_t)n * K + k] = __float2bfloat16(t[threadIdx.x][i]);
    }
}

__global__ void transpose_fp8(const float* __restrict__ in, uint8_t* __restrict__ out,
                              int K, int N)
{
    __shared__ float t[32][33];
    int nb = blockIdx.x * 32, kb = blockIdx.y * 32;
    for (int i = threadIdx.y; i < 32; i += 8) {
        int k = kb + i, n = nb + threadIdx.x;
        t[i][threadIdx.x] = (k < K && n < N) ? in[(size_t)k * N + n] : 0.f;
    }
    __syncthreads();
    for (int i = threadIdx.y; i < 32; i += 8) {
        int n = nb + i, k = kb + threadIdx.x;
        if (n < N && k < K)
            out[(size_t)n * K + k] =
                (uint8_t)__nv_cvt_float_to_fp8(t[threadIdx.x][i], __NV_SATFINITE, __NV_E4M3);
    }
}

// ---------------------------------------------------------------- LayerNorm -> bf16
__global__ void ln_kernel(const float* __restrict__ x, const float* __restrict__ g,
                          const float* __restrict__ be, __nv_bfloat16* __restrict__ out)
{
    __shared__ float sdata[256];
    int row = blockIdx.x;
    int tid = threadIdx.x;
    const float* xr = x + (size_t)row * DMODEL;
    float s = 0.f, ss = 0.f;
    for (int i = tid; i < DMODEL; i += 256) { float v = xr[i]; s += v; ss += v * v; }
    sdata[tid] = s; __syncthreads();
    for (int o = 128; o > 0; o >>= 1) { if (tid < o) sdata[tid] += sdata[tid + o]; __syncthreads(); }
    float mu = sdata[0] / (float)DMODEL;
    __syncthreads();
    sdata[tid] = ss; __syncthreads();
    for (int o = 128; o > 0; o >>= 1) { if (tid < o) sdata[tid] += sdata[tid + o]; __syncthreads(); }
    float var = sdata[0] / (float)DMODEL - mu * mu;
    float inv = rsqrtf(var + 1e-5f);
    for (int i = tid; i < DMODEL; i += 256) {
        float v = xr[i];
        out[(size_t)row * DMODEL + i] = __float2bfloat16((v - mu) * inv * g[i] + be[i]);
    }
}

// --------------------------------------------------- causal depthwise conv + silu v2
__global__ void conv_silu_kernel(const __nv_bfloat16* __restrict__ xz,
                                 const float* __restrict__ wf, const float* __restrict__ bf,
                                 const float* __restrict__ wb, const float* __restrict__ bb,
                                 float* __restrict__ xc, __nv_bfloat16* __restrict__ xcb)
{
    int idx = blockIdx.x * blockDim.x + threadIdx.x;
    int dir = idx >> 20;
    int r   = idx & ((1 << 20) - 1);
    int t4i = r >> 11;
    int d   = r & (DINNER - 1);
    int b   = t4i >> 8;
    int l0  = (t4i & 255) * 4;

    const float* w  = dir ? wb : wf;
    const float* bi = dir ? bb : bf;
    float w0 = w[d * 4 + 0], w1 = w[d * 4 + 1], w2 = w[d * 4 + 2], w3 = w[d * 4 + 3];
    float bias = bi[d];

    float v[7];
#pragma unroll
    for (int k = 0; k < 7; k++) {
        int lp = l0 - 3 + k;
        if (lp < 0) { v[k] = 0.f; continue; }
        int ll = dir ? (SEQ - 1 - lp) : lp;
        v[k] = __bfloat162float(xz[((size_t)(b * SEQ + ll)) * (2 * DINNER) + d]);
    }

    size_t obase = ((size_t)dir * TOKENS + (size_t)b * SEQ + l0) * DINNER + d;
#pragma unroll
    for (int m = 0; m < 4; m++) {
        float s = bias + w0 * v[m] + w1 * v[m + 1] + w2 * v[m + 2] + w3 * v[m + 3];
        float sig = 1.f / (1.f + __expf(-s));
        float o = s * sig;
        xc [obase + (size_t)m * DINNER] = o;
        xcb[obase + (size_t)m * DINNER] = __float2bfloat16(o);
    }
}

// ---------------------------------------------------------- split-K reduce
__global__ void reduce_split_kernel(const float* __restrict__ part,
                                    float* __restrict__ out, __nv_bfloat16* __restrict__ outb)
{
    int idx = blockIdx.x * blockDim.x + threadIdx.x;
    int dir = idx / (TOKENS * 96);
    int r   = idx - dir * (TOKENS * 96);
    const float* p = part + (size_t)dir * NSPLIT * TOKENS * 96 + r;
    float s = 0.f;
#pragma unroll
    for (int k = 0; k < NSPLIT; k++) s += p[(size_t)k * TOKENS * 96];
    out[idx] = s;
    int t = r / 96, col = r - t * 96;
    if (col < DTRANK)
        outb[((size_t)dir * TOKENS + t) * DTRANK + col] = __float2bfloat16(s);
}

// ----------------------------------------------------------------- scan v2 (-> e4m3)
__global__ void __launch_bounds__(256) scan_kernel(
    const float* __restrict__ xdbl,
    const float* __restrict__ dt,
    const float* __restrict__ xc,
    const float* __restrict__ Af, const float* __restrict__ Ab,
    const float* __restrict__ Df, const float* __restrict__ Db,
    uint8_t* __restrict__ ycat)
{
    const int blk  = blockIdx.x;
    const int dir  = blk >> 7;
    const int rem  = blk & 127;
    const int b    = rem >> 6;
    const int dblk = rem & 63;
    const int c    = threadIdx.x >> 3;
    const int ng   = threadIdx.x & 7;
    const int n0   = ng * 2;
    const int d    = dblk * 32 + c;

    const float* Alog = dir ? Ab : Af;
    const float a0 = -__expf(Alog[d * NSTATE + n0 + 0]);
    const float a1 = -__expf(Alog[d * NSTATE + n0 + 1]);
    const float dskip = (dir ? Db : Df)[d];

    const size_t chbase = ((size_t)dir * TOKENS + (size_t)b * SEQ) * DINNER + d;
    const float* dtp = dt + chbase;
    const float* xcp = xc + chbase;
    const float* xb  = xdbl + ((size_t)dir * TOKENS + (size_t)b * SEQ) * 96;

    float h0 = 0.f, h1 = 0.f;

    float  dt_c = dtp[0];
    float  xc_c = xcp[0];
    float2 B_c  = *(const float2*)(xb + 64 + n0);
    float2 C_c  = *(const float2*)(xb + 80 + n0);
    float  dt_n = dtp[DINNER];
    float  xc_n = xcp[DINNER];
    float2 B_n  = *(const float2*)(xb + 96 + 64 + n0);
    float2 C_n  = *(const float2*)(xb + 96 + 80 + n0);

    uint8_t* yout = ycat + ((size_t)b * SEQ) * (2 * DINNER) + dir * DINNER + d;
    const int rowstep = 2 * DINNER;

    for (int l = 0; l < SEQ; l++) {
        float dt_f = 0.f, xc_f = 0.f;
        float2 B_f = make_float2(0.f, 0.f), C_f = B_f;
        if (l + 2 < SEQ) {
            dt_f = dtp[(size_t)(l + 2) * DINNER];
            xc_f = xcp[(size_t)(l + 2) * DINNER];
            B_f  = *(const float2*)(xb + (size_t)(l + 2) * 96 + 64 + n0);
            C_f  = *(const float2*)(xb + (size_t)(l + 2) * 96 + 80 + n0);
        }

        const float dx = dt_c * xc_c;
        h0 = __expf(dt_c * a0) * h0 + dx * B_c.x;
        h1 = __expf(dt_c * a1) * h1 + dx * B_c.y;
        float y = h0 * C_c.x + h1 * C_c.y;

        y += __shfl_xor_sync(0xffffffffu, y, 1);
        y += __shfl_xor_sync(0xffffffffu, y, 2);
        y += __shfl_xor_sync(0xffffffffu, y, 4);

        if (ng == 0) {
            int row = dir ? (SEQ - 1 - l) : l;
            yout[(size_t)row * rowstep] =
                (uint8_t)__nv_cvt_float_to_fp8(y + xc_c * dskip, __NV_SATFINITE, __NV_E4M3);
        }

        dt_c = dt_n; xc_c = xc_n; B_c = B_n; C_c = C_n;
        dt_n = dt_f; xc_n = xc_f; B_n = B_f; C_n = C_f;
    }
}

// ================================================================ launch
extern "C" void kernel_launch(void* const* d_in, const int* in_sizes, int n_in,
                              void* d_out, int out_size)
{
    const float* x       = (const float*)d_in[0];
    const float* gamma   = (const float*)d_in[1];
    const float* beta    = (const float*)d_in[2];
    const float* in_w    = (const float*)d_in[3];
    const float* conv_w  = (const float*)d_in[4];
    const float* conv_b  = (const float*)d_in[5];
    const float* xproj_w = (const float*)d_in[6];
    const float* dt_w    = (const float*)d_in[7];
    const float* dt_b    = (const float*)d_in[8];
    const float* A_log   = (const float*)d_in[9];
    const float* D_skip  = (const float*)d_in[10];
    const float* conv_w_b  = (const float*)d_in[11];
    const float* conv_b_b  = (const float*)d_in[12];
    const float* xproj_w_b = (const float*)d_in[13];
    const float* dt_w_b    = (const float*)d_in[14];
    const float* dt_b_b    = (const float*)d_in[15];
    const float* A_log_b   = (const float*)d_in[16];
    const float* D_skip_b  = (const float*)d_in[17];
    const float* merge_w   = (const float*)d_in[18];
    const float* out_w     = (const float*)d_in[19];
    float* out = (float*)d_out;

    __nv_bfloat16 *p_lnb, *p_xz, *p_xcb, *p_xdblb, *p_ymb;
    __nv_bfloat16 *p_win, *p_wout, *p_wdt0, *p_wdt1, *p_wxp0, *p_wxp1;
    uint8_t *p_ycat8, *p_wmerge8;
    float *p_xc, *p_xpart, *p_xdbl, *p_dt;
    cudaGetSymbolAddress((void**)&p_lnb,    g_ln_bf);
    cudaGetSymbolAddress((void**)&p_xz,     g_xz);
    cudaGetSymbolAddress((void**)&p_xc,     g_xc);
    cudaGetSymbolAddress((void**)&p_xcb,    g_xc_bf);
    cudaGetSymbolAddress((void**)&p_xpart,  g_xpart);
    cudaGetSymbolAddress((void**)&p_xdbl,   g_xdbl);
    cudaGetSymbolAddress((void**)&p_xdblb,  g_xdbl_bf);
    cudaGetSymbolAddress((void**)&p_dt,     g_dt);
    cudaGetSymbolAddress((void**)&p_ycat8,  g_ycat8);
    cudaGetSymbolAddress((void**)&p_ymb,    g_ym_bf);
    cudaGetSymbolAddress((void**)&p_win,    g_w_in);
    cudaGetSymbolAddress((void**)&p_wmerge8,g_w_merge8);
    cudaGetSymbolAddress((void**)&p_wout,   g_w_out);
    cudaGetSymbolAddress((void**)&p_wdt0,   g_w_dt0);
    cudaGetSymbolAddress((void**)&p_wdt1,   g_w_dt1);
    cudaGetSymbolAddress((void**)&p_wxp0,   g_w_xp0);
    cudaGetSymbolAddress((void**)&p_wxp1,   g_w_xp1);

    dim3 tb(32, 8);

    // fork side branch
    cudaEventRecord(g_ev[0], 0);
    cudaStreamWaitEvent(g_s1, g_ev[0], 0);

    // main: LN; side: in_w transpose concurrently
    ln_kernel<<<TOKENS, 256>>>(x, gamma, beta, p_lnb);
    transpose_bf16<<<dim3(4096 / 32, 1024 / 32), tb, 0, g_s1>>>(in_w, p_win, 1024, 4096);
    cudaEventRecord(g_ev[6], g_s1);
    // side continues with merge_w transpose -> fp8 (overlaps in_proj/conv)
    transpose_fp8<<<dim3(2048 / 32, 4096 / 32), tb, 0, g_s1>>>(merge_w, p_wmerge8, 4096, 2048);

    // join in_w before in_proj
    cudaStreamWaitEvent(0, g_ev[6], 0);

    // in_proj: (T,1024)@(1024,4096) -> xz bf16   (w64)
    gemm_w64<<<dim3(32, 16), 128>>>(TOKENS, 4096, 1024,
        p_lnb, DMODEL, p_win, 1024, p_xz, 4096, 1, nullptr, 0);

    conv_silu_kernel<<<(2 * TOKENS * DINNER / 4) / 256, 256>>>(p_xz, conv_w, conv_b,
                                                               conv_w_b, conv_b_b,
                                                               p_xc, p_xcb);
    // remaining transposes on side stream
    transpose_bf16<<<dim3(3,         2048 / 32), tb, 0, g_s1>>>(xproj_w,   p_wxp0, 2048, 96);
    transpose_bf16<<<dim3(3,         2048 / 32), tb, 0, g_s1>>>(xproj_w_b, p_wxp1, 2048, 96);
    transpose_bf16<<<dim3(2048 / 32, 2),         tb, 0, g_s1>>>(dt_w,      p_wdt0, 64, 2048);
    transpose_bf16<<<dim3(2048 / 32, 2),         tb, 0, g_s1>>>(dt_w_b,    p_wdt1, 64, 2048);
    transpose_bf16<<<dim3(1024 / 32, 2048 / 32), tb, 0, g_s1>>>(out_w,     p_wout, 2048, 1024);
    cudaEventRecord(g_ev[1], g_s1);
    cudaStreamWaitEvent(0, g_ev[1], 0);

    // xproj both directions concurrently (v1 GEMM, split-K=8)
    cudaEventRecord(g_ev[2], 0);
    cudaStreamWaitEvent(g_s2, g_ev[2], 0);
    gemm_bf16<<<dim3(1, 16, NSPLIT), 256>>>(TOKENS, 96, DINNER / NSPLIT,
        p_xcb, DINNER, p_wxp0, 2048, p_xpart, 96, (size_t)TOKENS * 96,
        0, nullptr, 0);
    gemm_bf16<<<dim3(1, 16, NSPLIT), 256, 0, g_s2>>>(TOKENS, 96, DINNER / NSPLIT,
        p_xcb + (size_t)TOKENS * DINNER, DINNER, p_wxp1, 2048,
        p_xpart + (size_t)NSPLIT * TOKENS * 96, 96, (size_t)TOKENS * 96,
        0, nullptr, 0);
    cudaEventRecord(g_ev[3], g_s2);
    cudaStreamWaitEvent(0, g_ev[3], 0);

    reduce_split_kernel<<<(2 * TOKENS * 96) / 256, 256>>>(p_xpart, p_xdbl, p_xdblb);

    // dt GEMMs both directions concurrently (v1 GEMM)
    cudaEventRecord(g_ev[4], 0);
    cudaStreamWaitEvent(g_s2, g_ev[4], 0);
    gemm_bf16<<<dim3(16, 16, 1), 256>>>(TOKENS, DINNER, DTRANK,
        p_xdblb, DTRANK, p_wdt0, DTRANK, p_dt, DINNER, 0, 2, dt_b, 0);
    gemm_bf16<<<dim3(16, 16, 1), 256, 0, g_s2>>>(TOKENS, DINNER, DTRANK,
        p_xdblb + (size_t)TOKENS * DTRANK, DTRANK, p_wdt1, DTRANK,
        p_dt + (size_t)TOKENS * DINNER, DINNER, 0, 2, dt_b_b, 0);
    cudaEventRecord(g_ev[5], g_s2);
    cudaStreamWaitEvent(0, g_ev[5], 0);

    // selective scan -> ycat e4m3
    scan_kernel<<<256, 256>>>(p_xdbl, p_dt, p_xc, A_log, A_log_b, D_skip, D_skip_b, p_ycat8);

    // merge: (T,4096)@(4096,2048) in fp8, fused gate silu(z) -> ym bf16
    gemm_fp8<<<dim3(16, 16), 256>>>(TOKENS, DINNER, 2 * DINNER,
        p_ycat8, 2 * DINNER, p_wmerge8, 4096, p_ymb, DINNER, 3,
        p_xz + DINNER, 2 * DINNER);

    // out proj: (T,2048)@(2048,1024), fused residual -> d_out fp32   (w64)
    gemm_w64<<<dim3(8, 16), 128>>>(TOKENS, DMODEL, DINNER,
        p_ymb, DINNER, p_wout, 2048, out, DMODEL, 4, x, DMODEL);
}

// round 16
// speedup vs baseline: 1.0450x; 1.0450x over previous
#include <cuda_runtime.h>
#include <cuda_bf16.h>
#include <cstdint>

// Problem constants
#define BATCH   2
#define SEQ     1024
#define DMODEL  1024
#define DINNER  2048
#define DTRANK  64
#define NSTATE  16
#define TOKENS  (BATCH*SEQ)          // 2048
#define NSPLIT  8                    // split-K for xproj

// ---------------- scratch (device globals; no allocation allowed) ----------
__device__ __nv_bfloat16 g_ln_bf [TOKENS * DMODEL];
__device__ __nv_bfloat16 g_xz    [TOKENS * 2 * DINNER];     // bf16 (xs | z)
__device__ float         g_xc    [2 * TOKENS * DINNER];
__device__ __nv_bfloat16 g_xc_bf [2 * TOKENS * DINNER];
__device__ float         g_xpart [2 * NSPLIT * TOKENS * 96];
__device__ float         g_xdbl  [2 * TOKENS * 96];
__device__ __nv_bfloat16 g_xdbl_bf[2 * TOKENS * DTRANK];
__device__ float         g_dt    [2 * TOKENS * DINNER];
__device__ __nv_bfloat16 g_ycat  [TOKENS * 2 * DINNER];
__device__ __nv_bfloat16 g_ym_bf [TOKENS * DINNER];
// pre-transposed bf16 weights:  [N][K] layout (B operand rows are N, K-major)
__device__ __nv_bfloat16 g_w_in   [4096 * 1024];
__device__ __nv_bfloat16 g_w_merge[2048 * 4096];
__device__ __nv_bfloat16 g_w_out  [1024 * 2048];
__device__ __nv_bfloat16 g_w_dt0  [2048 * 64];
__device__ __nv_bfloat16 g_w_dt1  [2048 * 64];
__device__ __nv_bfloat16 g_w_xp0  [96 * 2048];
__device__ __nv_bfloat16 g_w_xp1  [96 * 2048];

// ---------------- streams/events for graph-parallel branches --------------
static cudaStream_t g_s1 = nullptr, g_s2 = nullptr;
static cudaEvent_t  g_ev[8];
static struct GInit {
    GInit() {
        cudaStreamCreateWithFlags(&g_s1, cudaStreamNonBlocking);
        cudaStreamCreateWithFlags(&g_s2, cudaStreamNonBlocking);
        for (int i = 0; i < 8; i++)
            cudaEventCreateWithFlags(&g_ev[i], cudaEventDisableTiming);
    }
} g_ginit;

#define PADROW 40      // bf16 elems per smem row (32 data + 8 pad); 80B

// ---------------- shared epilogue ---------------------------------------
// Modes: 0 fp32 out, 1 bf16 out, 2 softplus(v+aux[c]) fp32,
// 3 v*silu(bf16 aux[r,c]) -> bf16, 4 v+aux[r,c] fp32.
__device__ __forceinline__ void epi_store(
    int mode, float v, int r, int c, int ldc, int ldaux,
    float* Cf, __nv_bfloat16* Cb, const float* auxf, const __nv_bfloat16* auxb)
{
    if (mode == 0) {
        Cf[(size_t)r * ldc + c] = v;
    } else if (mode == 1) {
        Cb[(size_t)r * ldc + c] = __float2bfloat16(v);
    } else if (mode == 2) {
        v += auxf[c];
        v = (v > 20.f) ? v : log1pf(__expf(v));
        Cf[(size_t)r * ldc + c] = v;
    } else if (mode == 3) {
        float z = __bfloat162float(auxb[(size_t)r * ldaux + c]);
        v *= z / (1.f + __expf(-z));
        Cb[(size_t)r * ldc + c] = __float2bfloat16(v);
    } else {
        v += auxf[(size_t)r * ldaux + c];
        Cf[(size_t)r * ldc + c] = v;
    }
}

// ================================================================ GEMM v1
// 256 threads, 8 warps (2x4), warp tile 64x32. Proven baseline; used for
// xproj, dt, merge, out.
__global__ void __launch_bounds__(256) gemm_bf16(
    int M, int N, int Ksplit,
    const __nv_bfloat16* __restrict__ A, int lda,
    const __nv_bfloat16* __restrict__ B, int ldb,
    void* __restrict__ Cv, int ldc, size_t splitStride,
    int mode, const void* __restrict__ aux, int ldaux)
{
    __shared__ __nv_bfloat16 As[2][128 * PADROW];
    __shared__ __nv_bfloat16 Bs[2][128 * PADROW];

    const int tid  = threadIdx.x;
    const int lane = tid & 31;
    const int warp = tid >> 5;
    const int wm   = warp >> 2;
    const int wn   = warp & 3;
    const int g    = lane >> 2;
    const int t4   = lane & 3;

    const int bM = blockIdx.y * 128;
    const int bN = blockIdx.x * 128;
    const int kbase0 = blockIdx.z * Ksplit;
    const int niter = Ksplit / 32;

    const int r0s = tid >> 2;
    const int p0s = tid & 3;

    float acc[4][4][4];
#pragma unroll
    for (int i = 0; i < 4; i++)
#pragma unroll
        for (int j = 0; j < 4; j++)
#pragma unroll
            for (int q = 0; q < 4; q++) acc[i][j][q] = 0.f;

    const uint4 z4 = make_uint4(0, 0, 0, 0);

    {
        const int kb = kbase0;
#pragma unroll
        for (int i = 0; i < 2; i++) {
            int row = r0s + i * 64;
            uint4 va = *(const uint4*)(A + (size_t)(bM + row) * lda + kb + p0s * 8);
            *(uint4*)&As[0][row * PADROW + p0s * 8] = va;
            uint4 vb = (bN + row < N)
                ? *(const uint4*)(B + (size_t)(bN + row) * ldb + kb + p0s * 8) : z4;
            *(uint4*)&Bs[0][row * PADROW + p0s * 8] = vb;
        }
    }
    __syncthreads();

    for (int it = 0; it < niter; ++it) {
        const int buf = it & 1;
        const bool more = (it + 1) < niter;
        uint4 ra[2], rb[2];
        if (more) {
            const int kb = kbase0 + (it + 1) * 32;
#pragma unroll
            for (int i = 0; i < 2; i++) {
                int row = r0s + i * 64;
                ra[i] = *(const uint4*)(A + (size_t)(bM + row) * lda + kb + p0s * 8);
                rb[i] = (bN + row < N)
                    ? *(const uint4*)(B + (size_t)(bN + row) * ldb + kb + p0s * 8) : z4;
            }
        }

        const __nv_bfloat16* sa = As[buf];
        const __nv_bfloat16* sb = Bs[buf];
#pragma unroll
        for (int s = 0; s < 2; s++) {
            const int k0 = s * 16;
            uint32_t af[4][4];
#pragma unroll
            for (int im = 0; im < 4; im++) {
                int base = (wm * 64 + im * 16 + g) * PADROW + k0 + t4 * 2;
                af[im][0] = *(const uint32_t*)&sa[base];
                af[im][1] = *(const uint32_t*)&sa[base + 8 * PADROW];
                af[im][2] = *(const uint32_t*)&sa[base + 8];
                af[im][3] = *(const uint32_t*)&sa[base + 8 * PADROW + 8];
            }
            uint32_t bf[4][2];
#pragma unroll
            for (int in_ = 0; in_ < 4; in_++) {
                int base = (wn * 32 + in_ * 8 + g) * PADROW + k0 + t4 * 2;
                bf[in_][0] = *(const uint32_t*)&sb[base];
                bf[in_][1] = *(const uint32_t*)&sb[base + 8];
            }
#pragma unroll
            for (int im = 0; im < 4; im++)
#pragma unroll
                for (int in_ = 0; in_ < 4; in_++) {
                    asm volatile(
                        "mma.sync.aligned.m16n8k16.row.col.f32.bf16.bf16.f32 "
                        "{%0,%1,%2,%3}, {%4,%5,%6,%7}, {%8,%9}, {%0,%1,%2,%3};"
                        : "+f"(acc[im][in_][0]), "+f"(acc[im][in_][1]),
                          "+f"(acc[im][in_][2]), "+f"(acc[im][in_][3])
                        : "r"(af[im][0]), "r"(af[im][1]), "r"(af[im][2]), "r"(af[im][3]),
                          "r"(bf[in_][0]), "r"(bf[in_][1]));
                }
        }

        if (more) {
            const int nb = buf ^ 1;
#pragma unroll
            for (int i = 0; i < 2; i++) {
                int row = r0s + i * 64;
                *(uint4*)&As[nb][row * PADROW + p0s * 8] = ra[i];
                *(uint4*)&Bs[nb][row * PADROW + p0s * 8] = rb[i];
            }
        }
        __syncthreads();
    }

    float* Cf = (float*)Cv + (size_t)blockIdx.z * splitStride;
    __nv_bfloat16* Cb = (__nv_bfloat16*)Cv;
    const float* auxf = (const float*)aux;
    const __nv_bfloat16* auxb = (const __nv_bfloat16*)aux;
#pragma unroll
    for (int im = 0; im < 4; im++) {
        int rr0 = bM + wm * 64 + im * 16 + g;
#pragma unroll
        for (int in_ = 0; in_ < 4; in_++) {
            int cc0 = bN + wn * 32 + in_ * 8 + t4 * 2;
#pragma unroll
            for (int q = 0; q < 4; q++) {
                int r = rr0 + (q >> 1) * 8;
                int c = cc0 + (q & 1);
                if (c >= N) continue;
                epi_store(mode, acc[im][in_][q], r, c, ldc, ldaux, Cf, Cb, auxf, auxb);
            }
        }
    }
}

// ================================================================ GEMM w64
// 128 threads, 4 warps (2x2), warp tile 64x64. Used ONLY for in_proj
// (per-kernel verified faster: 91.6 vs 97.9 us across three profiles).
__global__ void __launch_bounds__(128) gemm_w64(
    int M, int N, int Kfull,
    const __nv_bfloat16* __restrict__ A, int lda,
    const __nv_bfloat16* __restrict__ B, int ldb,
    void* __restrict__ Cv, int ldc,
    int mode, const void* __restrict__ aux, int ldaux)
{
    __shared__ __nv_bfloat16 As[2][128 * PADROW];
    __shared__ __nv_bfloat16 Bs[2][128 * PADROW];

    const int tid  = threadIdx.x;
    const int lane = tid & 31;
    const int warp = tid >> 5;
    const int wm   = warp >> 1;
    const int wn   = warp & 1;
    const int g    = lane >> 2;
    const int t4   = lane & 3;

    const int bM = blockIdx.y * 128;
    const int bN = blockIdx.x * 128;
    const int niter = Kfull / 32;

    const int r0s = tid >> 2;
    const int p0s = tid & 3;

    float acc[4][8][4];
#pragma unroll
    for (int i = 0; i < 4; i++)
#pragma unroll
        for (int j = 0; j < 8; j++)
#pragma unroll
            for (int q = 0; q < 4; q++) acc[i][j][q] = 0.f;

    const uint4 z4 = make_uint4(0, 0, 0, 0);

    {
#pragma unroll
        for (int i = 0; i < 4; i++) {
            int row = r0s + i * 32;
            uint4 va = *(const uint4*)(A + (size_t)(bM + row) * lda + p0s * 8);
            *(uint4*)&As[0][row * PADROW + p0s * 8] = va;
            uint4 vb = (bN + row < N)
                ? *(const uint4*)(B + (size_t)(bN + row) * ldb + p0s * 8) : z4;
            *(uint4*)&Bs[0][row * PADROW + p0s * 8] = vb;
        }
    }
    __syncthreads();

    for (int it = 0; it < niter; ++it) {
        const int buf = it & 1;
        const bool more = (it + 1) < niter;
        uint4 ra[4], rb[4];
        if (more) {
            const int kb = (it + 1) * 32;
#pragma unroll
            for (int i = 0; i < 4; i++) {
                int row = r0s + i * 32;
                ra[i] = *(const uint4*)(A + (size_t)(bM + row) * lda + kb + p0s * 8);
                rb[i] = (bN + row < N)
                    ? *(const uint4*)(B + (size_t)(bN + row) * ldb + kb + p0s * 8) : z4;
            }
        }

        const __nv_bfloat16* sa = As[buf];
        const __nv_bfloat16* sb = Bs[buf];
#pragma unroll
        for (int s = 0; s < 2; s++) {
            const int k0 = s * 16;
            uint32_t af[4][4];
#pragma unroll
            for (int im = 0; im < 4; im++) {
                int base = (wm * 64 + im * 16 + g) * PADROW + k0 + t4 * 2;
                af[im][0] = *(const uint32_t*)&sa[base];
                af[im][1] = *(const uint32_t*)&sa[base + 8 * PADROW];
                af[im][2] = *(const uint32_t*)&sa[base + 8];
                af[im][3] = *(const uint32_t*)&sa[base + 8 * PADROW + 8];
            }
            uint32_t bf[8][2];
#pragma unroll
            for (int in_ = 0; in_ < 8; in_++) {
                int base = (wn * 64 + in_ * 8 + g) * PADROW + k0 + t4 * 2;
                bf[in_][0] = *(const uint32_t*)&sb[base];
                bf[in_][1] = *(const uint32_t*)&sb[base + 8];
            }
#pragma unroll
            for (int im = 0; im < 4; im++)
#pragma unroll
                for (int in_ = 0; in_ < 8; in_++) {
                    asm volatile(
                        "mma.sync.aligned.m16n8k16.row.col.f32.bf16.bf16.f32 "
                        "{%0,%1,%2,%3}, {%4,%5,%6,%7}, {%8,%9}, {%0,%1,%2,%3};"
                        : "+f"(acc[im][in_][0]), "+f"(acc[im][in_][1]),
                          "+f"(acc[im][in_][2]), "+f"(acc[im][in_][3])
                        : "r"(af[im][0]), "r"(af[im][1]), "r"(af[im][2]), "r"(af[im][3]),
                          "r"(bf[in_][0]), "r"(bf[in_][1]));
                }
        }

        if (more) {
            const int nb = buf ^ 1;
#pragma unroll
            for (int i = 0; i < 4; i++) {
                int row = r0s + i * 32;
                *(uint4*)&As[nb][row * PADROW + p0s * 8] = ra[i];
                *(uint4*)&Bs[nb][row * PADROW + p0s * 8] = rb[i];
            }
        }
        __syncthreads();
    }

    float* Cf = (float*)Cv;
    __nv_bfloat16* Cb = (__nv_bfloat16*)Cv;
    const float* auxf = (const float*)aux;
    const __nv_bfloat16* auxb = (const __nv_bfloat16*)aux;
#pragma unroll
    for (int im = 0; im < 4; im++) {
        int rr0 = bM + wm * 64 + im * 16 + g;
#pragma unroll
        for (int in_ = 0; in_ < 8; in_++) {
            int cc0 = bN + wn * 64 + in_ * 8 + t4 * 2;
#pragma unroll
            for (int q = 0; q < 4; q++) {
                int r = rr0 + (q >> 1) * 8;
                int c = cc0 + (q & 1);
                if (c >= N) continue;
                epi_store(mode, acc[im][in_][q], r, c, ldc, ldaux, Cf, Cb, auxf, auxb);
            }
        }
    }
}

// ============================================================ weight transpose
__global__ void transpose_bf16(const float* __restrict__ in, __nv_bfloat16* __restrict__ out,
                               int K, int N)
{
    __shared__ float t[32][33];
    int nb = blockIdx.x * 32, kb = blockIdx.y * 32;
    for (int i = threadIdx.y; i < 32; i += 8) {
        int k = kb + i, n = nb + threadIdx.x;
        t[i][threadIdx.x] = (k < K && n < N) ? in[(size_t)k * N + n] : 0.f;
    }
    __syncthreads();
    for (int i = threadIdx.y; i < 32; i += 8) {
        int n = nb + i, k = kb + threadIdx.x;
        if (n < N && k < K) out[(size_t)n * K + k] = __float2bfloat16(t[threadIdx.x][i]);
    }
}

// ---------------------------------------------------------------- LayerNorm -> bf16
__global__ void ln_kernel(const float* __restrict__ x, const float* __restrict__ g,
                          const float* __restrict__ be, __nv_bfloat16* __restrict__ out)
{
    __shared__ float sdata[256];
    int row = blockIdx.x;
    int tid = threadIdx.x;
    const float* xr = x + (size_t)row * DMODEL;
    float s = 0.f, ss = 0.f;
    for (int i = tid; i < DMODEL; i += 256) { float v = xr[i]; s += v; ss += v * v; }
    sdata[tid] = s; __syncthreads();
    for (int o = 128; o > 0; o >>= 1) { if (tid < o) sdata[tid] += sdata[tid + o]; __syncthreads(); }
    float mu = sdata[0] / (float)DMODEL;
    __syncthreads();
    sdata[tid] = ss; __syncthreads();
    for (int o = 128; o > 0; o >>= 1) { if (tid < o) sdata[tid] += sdata[tid + o]; __syncthreads(); }
    float var = sdata[0] / (float)DMODEL - mu * mu;
    float inv = rsqrtf(var + 1e-5f);
    for (int i = tid; i < DMODEL; i += 256) {
        float v = xr[i];
        out[(size_t)row * DMODEL + i] = __float2bfloat16((v - mu) * inv * g[i] + be[i]);
    }
}

// --------------------------------------------------- causal depthwise conv + silu v2
__global__ void conv_silu_kernel(const __nv_bfloat16* __restrict__ xz,
                                 const float* __restrict__ wf, const float* __restrict__ bf,
                                 const float* __restrict__ wb, const float* __restrict__ bb,
                                 float* __restrict__ xc, __nv_bfloat16* __restrict__ xcb)
{
    int idx = blockIdx.x * blockDim.x + threadIdx.x;
    int dir = idx >> 20;
    int r   = idx & ((1 << 20) - 1);
    int t4i = r >> 11;
    int d   = r & (DINNER - 1);
    int b   = t4i >> 8;
    int l0  = (t4i & 255) * 4;

    const float* w  = dir ? wb : wf;
    const float* bi = dir ? bb : bf;
    float w0 = w[d * 4 + 0], w1 = w[d * 4 + 1], w2 = w[d * 4 + 2], w3 = w[d * 4 + 3];
    float bias = bi[d];

    float v[7];
#pragma unroll
    for (int k = 0; k < 7; k++) {
        int lp = l0 - 3 + k;
        if (lp < 0) { v[k] = 0.f; continue; }
        int ll = dir ? (SEQ - 1 - lp) : lp;
        v[k] = __bfloat162float(xz[((size_t)(b * SEQ + ll)) * (2 * DINNER) + d]);
    }

    size_t obase = ((size_t)dir * TOKENS + (size_t)b * SEQ + l0) * DINNER + d;
#pragma unroll
    for (int m = 0; m < 4; m++) {
        float s = bias + w0 * v[m] + w1 * v[m + 1] + w2 * v[m + 2] + w3 * v[m + 3];
        float sig = 1.f / (1.f + __expf(-s));
        float o = s * sig;
        xc [obase + (size_t)m * DINNER] = o;
        xcb[obase + (size_t)m * DINNER] = __float2bfloat16(o);
    }
}

// ---------------------------------------------------------- split-K reduce
__global__ void reduce_split_kernel(const float* __restrict__ part,
                                    float* __restrict__ out, __nv_bfloat16* __restrict__ outb)
{
    int idx = blockIdx.x * blockDim.x + threadIdx.x;
    int dir = idx / (TOKENS * 96);
    int r   = idx - dir * (TOKENS * 96);
    const float* p = part + (size_t)dir * NSPLIT * TOKENS * 96 + r;
    float s = 0.f;
#pragma unroll
    for (int k = 0; k < NSPLIT; k++) s += p[(size_t)k * TOKENS * 96];
    out[idx] = s;
    int t = r / 96, col = r - t * 96;
    if (col < DTRANK)
        outb[((size_t)dir * TOKENS + t) * DTRANK + col] = __float2bfloat16(s);
}

// ----------------------------------------------------------------- scan v2
__global__ void __launch_bounds__(256) scan_kernel(
    const float* __restrict__ xdbl,
    const float* __restrict__ dt,
    const float* __restrict__ xc,
    const float* __restrict__ Af, const float* __restrict__ Ab,
    const float* __restrict__ Df, const float* __restrict__ Db,
    __nv_bfloat16* __restrict__ ycat)
{
    const int blk  = blockIdx.x;
    const int dir  = blk >> 7;
    const int rem  = blk & 127;
    const int b    = rem >> 6;
    const int dblk = rem & 63;
    const int c    = threadIdx.x >> 3;
    const int ng   = threadIdx.x & 7;
    const int n0   = ng * 2;
    const int d    = dblk * 32 + c;

    const float* Alog = dir ? Ab : Af;
    const float a0 = -__expf(Alog[d * NSTATE + n0 + 0]);
    const float a1 = -__expf(Alog[d * NSTATE + n0 + 1]);
    const float dskip = (dir ? Db : Df)[d];

    const size_t chbase = ((size_t)dir * TOKENS + (size_t)b * SEQ) * DINNER + d;
    const float* dtp = dt + chbase;
    const float* xcp = xc + chbase;
    const float* xb  = xdbl + ((size_t)dir * TOKENS + (size_t)b * SEQ) * 96;

    float h0 = 0.f, h1 = 0.f;

    float  dt_c = dtp[0];
    float  xc_c = xcp[0];
    float2 B_c  = *(const float2*)(xb + 64 + n0);
    float2 C_c  = *(const float2*)(xb + 80 + n0);
    float  dt_n = dtp[DINNER];
    float  xc_n = xcp[DINNER];
    float2 B_n  = *(const float2*)(xb + 96 + 64 + n0);
    float2 C_n  = *(const float2*)(xb + 96 + 80 + n0);

    __nv_bfloat16* yout = ycat + ((size_t)b * SEQ) * (2 * DINNER) + dir * DINNER + d;
    const int rowstep = 2 * DINNER;

    for (int l = 0; l < SEQ; l++) {
        float dt_f = 0.f, xc_f = 0.f;
        float2 B_f = make_float2(0.f, 0.f), C_f = B_f;
        if (l + 2 < SEQ) {
            dt_f = dtp[(size_t)(l + 2) * DINNER];
            xc_f = xcp[(size_t)(l + 2) * DINNER];
            B_f  = *(const float2*)(xb + (size_t)(l + 2) * 96 + 64 + n0);
            C_f  = *(const float2*)(xb + (size_t)(l + 2) * 96 + 80 + n0);
        }

        const float dx = dt_c * xc_c;
        h0 = __expf(dt_c * a0) * h0 + dx * B_c.x;
        h1 = __expf(dt_c * a1) * h1 + dx * B_c.y;
        float y = h0 * C_c.x + h1 * C_c.y;

        y += __shfl_xor_sync(0xffffffffu, y, 1);
        y += __shfl_xor_sync(0xffffffffu, y, 2);
        y += __shfl_xor_sync(0xffffffffu, y, 4);

        if (ng == 0) {
            int row = dir ? (SEQ - 1 - l) : l;
            yout[(size_t)row * rowstep] = __float2bfloat16(y + xc_c * dskip);
        }

        dt_c = dt_n; xc_c = xc_n; B_c = B_n; C_c = C_n;
        dt_n = dt_f; xc_n = xc_f; B_n = B_f; C_n = C_f;
    }
}

// ================================================================ launch
extern "C" void kernel_launch(void* const* d_in, const int* in_sizes, int n_in,
                              void* d_out, int out_size)
{
    const float* x       = (const float*)d_in[0];
    const float* gamma   = (const float*)d_in[1];
    const float* beta    = (const float*)d_in[2];
    const float* in_w    = (const float*)d_in[3];
    const float* conv_w  = (const float*)d_in[4];
    const float* conv_b  = (const float*)d_in[5];
    const float* xproj_w = (const float*)d_in[6];
    const float* dt_w    = (const float*)d_in[7];
    const float* dt_b    = (const float*)d_in[8];
    const float* A_log   = (const float*)d_in[9];
    const float* D_skip  = (const float*)d_in[10];
    const float* conv_w_b  = (const float*)d_in[11];
    const float* conv_b_b  = (const float*)d_in[12];
    const float* xproj_w_b = (const float*)d_in[13];
    const float* dt_w_b    = (const float*)d_in[14];
    const float* dt_b_b    = (const float*)d_in[15];
    const float* A_log_b   = (const float*)d_in[16];
    const float* D_skip_b  = (const float*)d_in[17];
    const float* merge_w   = (const float*)d_in[18];
    const float* out_w     = (const float*)d_in[19];
    float* out = (float*)d_out;

    __nv_bfloat16 *p_lnb, *p_xz, *p_xcb, *p_xdblb, *p_ycat, *p_ymb;
    __nv_bfloat16 *p_win, *p_wmerge, *p_wout, *p_wdt0, *p_wdt1, *p_wxp0, *p_wxp1;
    float *p_xc, *p_xpart, *p_xdbl, *p_dt;
    cudaGetSymbolAddress((void**)&p_lnb,   g_ln_bf);
    cudaGetSymbolAddress((void**)&p_xz,    g_xz);
    cudaGetSymbolAddress((void**)&p_xc,    g_xc);
    cudaGetSymbolAddress((void**)&p_xcb,   g_xc_bf);
    cudaGetSymbolAddress((void**)&p_xpart, g_xpart);
    cudaGetSymbolAddress((void**)&p_xdbl,  g_xdbl);
    cudaGetSymbolAddress((void**)&p_xdblb, g_xdbl_bf);
    cudaGetSymbolAddress((void**)&p_dt,    g_dt);
    cudaGetSymbolAddress((void**)&p_ycat,  g_ycat);
    cudaGetSymbolAddress((void**)&p_ymb,   g_ym_bf);
    cudaGetSymbolAddress((void**)&p_win,   g_w_in);
    cudaGetSymbolAddress((void**)&p_wmerge,g_w_merge);
    cudaGetSymbolAddress((void**)&p_wout,  g_w_out);
    cudaGetSymbolAddress((void**)&p_wdt0,  g_w_dt0);
    cudaGetSymbolAddress((void**)&p_wdt1,  g_w_dt1);
    cudaGetSymbolAddress((void**)&p_wxp0,  g_w_xp0);
    cudaGetSymbolAddress((void**)&p_wxp1,  g_w_xp1);

    dim3 tb(32, 8);

    // fork side branch
    cudaEventRecord(g_ev[0], 0);
    cudaStreamWaitEvent(g_s1, g_ev[0], 0);

    // main: LN; side: in_w transpose concurrently
    ln_kernel<<<TOKENS, 256>>>(x, gamma, beta, p_lnb);
    transpose_bf16<<<dim3(4096 / 32, 1024 / 32), tb, 0, g_s1>>>(in_w, p_win, 1024, 4096);
    cudaEventRecord(g_ev[6], g_s1);
    // side continues with merge_w transpose (overlaps in_proj/conv)
    transpose_bf16<<<dim3(2048 / 32, 4096 / 32), tb, 0, g_s1>>>(merge_w, p_wmerge, 4096, 2048);

    // join in_w before in_proj
    cudaStreamWaitEvent(0, g_ev[6], 0);

    // in_proj: (T,1024)@(1024,4096) -> xz bf16   (w64)
    gemm_w64<<<dim3(32, 16), 128>>>(TOKENS, 4096, 1024,
        p_lnb, DMODEL, p_win, 1024, p_xz, 4096, 1, nullptr, 0);

    conv_silu_kernel<<<(2 * TOKENS * DINNER / 4) / 256, 256>>>(p_xz, conv_w, conv_b,
                                                               conv_w_b, conv_b_b,
                                                               p_xc, p_xcb);
    // remaining transposes on side stream
    transpose_bf16<<<dim3(3,         2048 / 32), tb, 0, g_s1>>>(xproj_w,   p_wxp0, 2048, 96);
    transpose_bf16<<<dim3(3,         2048 / 32), tb, 0, g_s1>>>(xproj_w_b, p_wxp1, 2048, 96);
    transpose_bf16<<<dim3(2048 / 32, 2),         tb, 0, g_s1>>>(dt_w,      p_wdt0, 64, 2048);
    transpose_bf16<<<dim3(2048 / 32, 2),         tb, 0, g_s1>>>(dt_w_b,    p_wdt1, 64, 2048);
    transpose_bf16<<<dim3(1024 / 32, 2048 / 32), tb, 0, g_s1>>>(out_w,     p_wout, 2048, 1024);
    cudaEventRecord(g_ev[1], g_s1);
    cudaStreamWaitEvent(0, g_ev[1], 0);

    // xproj both directions concurrently (v1 GEMM, split-K=8)
    cudaEventRecord(g_ev[2], 0);
    cudaStreamWaitEvent(g_s2, g_ev[2], 0);
    gemm_bf16<<<dim3(1, 16, NSPLIT), 256>>>(TOKENS, 96, DINNER / NSPLIT,
        p_xcb, DINNER, p_wxp0, 2048, p_xpart, 96, (size_t)TOKENS * 96,
        0, nullptr, 0);
    gemm_bf16<<<dim3(1, 16, NSPLIT), 256, 0, g_s2>>>(TOKENS, 96, DINNER / NSPLIT,
        p_xcb + (size_t)TOKENS * DINNER, DINNER, p_wxp1, 2048,
        p_xpart + (size_t)NSPLIT * TOKENS * 96, 96, (size_t)TOKENS * 96,
        0, nullptr, 0);
    cudaEventRecord(g_ev[3], g_s2);
    cudaStreamWaitEvent(0, g_ev[3], 0);

    reduce_split_kernel<<<(2 * TOKENS * 96) / 256, 256>>>(p_xpart, p_xdbl, p_xdblb);

    // dt GEMMs both directions concurrently (v1 GEMM)
    cudaEventRecord(g_ev[4], 0);
    cudaStreamWaitEvent(g_s2, g_ev[4], 0);
    gemm_bf16<<<dim3(16, 16, 1), 256>>>(TOKENS, DINNER, DTRANK,
        p_xdblb, DTRANK, p_wdt0, DTRANK, p_dt, DINNER, 0, 2, dt_b, 0);
    gemm_bf16<<<dim3(16, 16, 1), 256, 0, g_s2>>>(TOKENS, DINNER, DTRANK,
        p_xdblb + (size_t)TOKENS * DTRANK, DTRANK, p_wdt1, DTRANK,
        p_dt + (size_t)TOKENS * DINNER, DINNER, 0, 2, dt_b_b, 0);
    cudaEventRecord(g_ev[5], g_s2);
    cudaStreamWaitEvent(0, g_ev[5], 0);

    // selective scan -> ycat bf16
    scan_kernel<<<256, 256>>>(p_xdbl, p_dt, p_xc, A_log, A_log_b, D_skip, D_skip_b, p_ycat);

    // merge: (T,4096)@(4096,2048), fused gate silu(z) -> ym bf16   (v1)
    gemm_bf16<<<dim3(16, 16, 1), 256>>>(TOKENS, DINNER, 2 * DINNER,
        p_ycat, 2 * DINNER, p_wmerge, 4096, p_ymb, DINNER, 0, 3,
        p_xz + DINNER, 2 * DINNER);

    // out proj: (T,2048)@(2048,1024), fused residual -> d_out fp32   (v1)
    gemm_bf16<<<dim3(8, 16, 1), 256>>>(TOKENS, DMODEL, DINNER,
        p_ymb, DINNER, p_wout, 2048, out, DMODEL, 0, 4, x, DMODEL);
}